// round 14
// baseline (speedup 1.0000x reference)
#include <cuda_runtime.h>
#include <cstdint>

#define B 32
#define D 128
#define DIN 2048
#define A 7
#define K 5
#define TR 128           // reps rows per tile (= GEMM M)
#define GBLK 148         // 1 CTA/SM, one wave (required for last-block finalize)
#define PITCH 33         // staging: 16B units per row = 132 floats
#define NSTG 2           // pipeline depth
#define APITCH 272       // bf16 A row pitch (bytes) -> conflict-free fragment LDS.32
#define KSPLIT 64
#define KSLICE (DIN / KSPLIT)   // 32
#define BT 16            // batches per enc block

typedef unsigned long long ull;

// ---------------- smem layout (bytes) ----------------
#define OFF_AN   0              // 32 floats
#define OFF_RN   128            // 128 floats
#define OFF_SQ   1024           // 32 x 132 floats = 16896
#define OFF_ABF  17920          // 128 x APITCH bf16 tile = 34816
#define OFF_STG  52736          // 2 x (128 x 33 u2 = 67584)
#define STG_SZ   67584
#define SMEM_TOTAL (OFF_STG + NSTG * STG_SZ)   // 187904

// ---------------- scratch ----------------
__device__ float g_partial[KSPLIT * B * D];
__device__ float g_brep[B * D];
__device__ float g_anorm[B];
__device__ float g_cand_d[B * GBLK * K];   // [batch][block][5] (approx sq)
__device__ int   g_cand_i[B * GBLK * K];
__device__ unsigned g_done;

// ---------------- helpers ----------------
__device__ __forceinline__ unsigned pack_bf16x2(float lo_elem, float hi_elem) {
    unsigned r;
    asm("cvt.rn.bf16x2.f32 %0, %1, %2;" : "=r"(r) : "f"(hi_elem), "f"(lo_elem));
    return r;
}

__device__ __forceinline__ void mma_bf16(float* c, unsigned a0, unsigned a1,
                                         unsigned a2, unsigned a3,
                                         unsigned b0, unsigned b1) {
    asm volatile(
        "mma.sync.aligned.m16n8k16.row.col.f32.bf16.bf16.f32 "
        "{%0,%1,%2,%3}, {%4,%5,%6,%7}, {%8,%9}, {%0,%1,%2,%3};"
        : "+f"(c[0]), "+f"(c[1]), "+f"(c[2]), "+f"(c[3])
        : "r"(a0), "r"(a1), "r"(a2), "r"(a3), "r"(b0), "r"(b1));
}

// NaN-safe top-5 insert (ascending)
__device__ __forceinline__ void ins5(float sq, int idx, float* d, int* ix)
{
    if (!(sq < d[4])) return;
    if (sq < d[2]) {
        d[4] = d[3]; ix[4] = ix[3]; d[3] = d[2]; ix[3] = ix[2];
        if (sq < d[1]) {
            d[2] = d[1]; ix[2] = ix[1];
            if (sq < d[0]) { d[1] = d[0]; ix[1] = ix[0]; d[0] = sq; ix[0] = idx; }
            else           { d[1] = sq; ix[1] = idx; }
        } else { d[2] = sq; ix[2] = idx; }
    } else {
        if (sq < d[3]) { d[4] = d[3]; ix[4] = ix[3]; d[3] = sq; ix[3] = idx; }
        else           { d[4] = sq; ix[4] = idx; }
    }
}

// NaN-safe top-8 bubble insert (ascending, fully unrolled -> registers)
__device__ __forceinline__ void ins8(float v, int idx, float* d, int* ix)
{
    if (!(v < d[7])) return;
    d[7] = v; ix[7] = idx;
#pragma unroll
    for (int k = 7; k > 0; k--) {
        if (d[k] < d[k - 1]) {
            float tv = d[k]; d[k] = d[k - 1]; d[k - 1] = tv;
            int   tn = ix[k]; ix[k] = ix[k - 1]; ix[k - 1] = tn;
        }
    }
}

// ---------------- kernel 1: encoder split-K GEMM (16-batch tile) ----------------
__global__ void enc_partial_kernel(const float* __restrict__ x,
                                   const float* __restrict__ W)
{
    const int ks = blockIdx.x;
    const int bt = blockIdx.y;
    const int d  = threadIdx.x;
    __shared__ float xs[BT][KSLICE];
    for (int i = d; i < BT * KSLICE; i += 128) {
        const int j = i >> 5, kk = i & 31;
        xs[j][kk] = x[(bt * BT + j) * DIN + ks * KSLICE + kk];
    }
    __syncthreads();
    const float* Wp = W + (size_t)(ks * KSLICE) * D + d;
    float acc[BT];
#pragma unroll
    for (int j = 0; j < BT; j++) acc[j] = 0.f;
#pragma unroll
    for (int i = 0; i < KSLICE; i++) {
        const float wv = Wp[(size_t)i * D];
#pragma unroll
        for (int j = 0; j < BT; j++) acc[j] = fmaf(xs[j][i], wv, acc[j]);
    }
#pragma unroll
    for (int j = 0; j < BT; j++)
        g_partial[(ks * B + bt * BT + j) * D + d] = acc[j];
}

// ---------------- kernel 1b: reduce partials, add bias, |a|^2 ----------------
__global__ void enc_reduce_kernel(const float* __restrict__ b_enc)
{
    const int b = blockIdx.x;
    const int d = threadIdx.x;
    float r = b_enc[d];
#pragma unroll
    for (int ks = 0; ks < KSPLIT; ks++)
        r += g_partial[(ks * B + b) * D + d];
    g_brep[b * D + d] = r;

    float s = r * r;
#pragma unroll
    for (int o = 16; o; o >>= 1) s += __shfl_xor_sync(0xffffffffu, s, o);
    __shared__ float ws[4];
    if ((d & 31) == 0) ws[d >> 5] = s;
    __syncthreads();
    if (d == 0) g_anorm[b] = ws[0] + ws[1] + ws[2] + ws[3];
}

// ---------------- cp.async staging tile load (zero-fill OOB rows) ----------------
__device__ __forceinline__ void load_tile_async(char* sm, int buf,
                                                const float* __restrict__ reps,
                                                int row0, int N, int tid)
{
    float4* bp = (float4*)(sm + OFF_STG + buf * STG_SZ);
#pragma unroll
    for (int j = 0; j < 16; j++) {
        const int c   = tid + j * 256;
        const int row = c >> 5;
        const int col = c & 31;
        const int gr  = row0 + row;
        const int grc = (gr < N) ? gr : 0;
        const int sz  = (gr < N) ? 16 : 0;         // src-size 0 -> zero fill
        const float4* src = (const float4*)reps + (size_t)grc * 32 + col;
        unsigned dst = (unsigned)__cvta_generic_to_shared(bp + row * PITCH + col);
        asm volatile("cp.async.cg.shared.global [%0], [%1], 16, %2;"
                     :: "r"(dst), "l"(src), "r"(sz) : "memory");
    }
}

// ---------------- kernel 2: bf16 single-pass screening cdist + exact refine ----------------
// 256 threads, 8 warps. Warp (wm = w&3, wn = w>>2) owns m-rows [wm*32,+32) x n-cols [wn*16,+16).
// B fragments (tile-invariant bf16) live in 32 registers/thread; A converted per tile.
__global__ void __launch_bounds__(256) dist_topk_kernel(
    const float* __restrict__ reps, int N,
    const float* __restrict__ actions, float* __restrict__ out)
{
    extern __shared__ char sm[];
    float* an_s = (float*)(sm + OFF_AN);
    float* rn_s = (float*)(sm + OFF_RN);
    float* sq_s = (float*)(sm + OFF_SQ);       // [n=32][m=132]
    char*  abf  = sm + OFF_ABF;                // bf16 A tile, pitch 272B

    const int tid  = threadIdx.x;
    const int lane = tid & 31;
    const int w    = tid >> 5;
    const int gid  = lane >> 2;
    const int t4   = lane & 3;
    const int wm   = w & 3;
    const int wn   = w >> 2;

    if (tid < 32) an_s[tid] = g_anorm[tid];

    // ---- B fragments: tile-invariant bf16, 32 regs (b0,b1 per ks per nf2) ----
    unsigned b0r[8][2], b1r[8][2];
#pragma unroll
    for (int ks = 0; ks < 8; ks++)
#pragma unroll
        for (int nf2 = 0; nf2 < 2; nf2++) {
            const int n  = wn * 16 + nf2 * 8 + gid;
            const int k0 = ks * 16 + t4 * 2;
            b0r[ks][nf2] = pack_bf16x2(g_brep[n * D + k0],     g_brep[n * D + k0 + 1]);
            b1r[ks][nf2] = pack_bf16x2(g_brep[n * D + k0 + 8], g_brep[n * D + k0 + 9]);
        }

    float td[5]; int ti[5];
#pragma unroll
    for (int j = 0; j < 5; j++) { td[j] = 3.4e38f; ti[j] = 0; }

    const int ntiles = (N + TR - 1) / TR;

    // prologue: first tile in flight
    load_tile_async(sm, 0, reps, blockIdx.x * TR, N, tid);
    asm volatile("cp.async.commit_group;" ::: "memory");

    int ib = 0;
    for (int t = blockIdx.x; t < ntiles; t += GBLK) {
        if (t + GBLK < ntiles)
            load_tile_async(sm, 1 - ib, reps, (t + GBLK) * TR, N, tid);
        asm volatile("cp.async.commit_group;" ::: "memory");
        asm volatile("cp.async.wait_group 1;" ::: "memory");   // current tile ready
        __syncthreads();

        const float* stgf = (const float*)(sm + OFF_STG + ib * STG_SZ);

        // ---- convert fp32 tile -> bf16 (pitch 272B) + exact fp32 row norms ----
        {
            const int row = tid >> 1, h = tid & 1;   // 2 threads/row, 64 floats each
            const float4* rp = (const float4*)stgf + row * PITCH + h * 16;
            ull* ap = (ull*)(abf + row * APITCH + h * 128);
            float nsum = 0.f;
#pragma unroll
            for (int j = 0; j < 16; j++) {
                const float4 v = rp[j];
                nsum += v.x * v.x + v.y * v.y + v.z * v.z + v.w * v.w;
                const unsigned r0 = pack_bf16x2(v.x, v.y);
                const unsigned r1 = pack_bf16x2(v.z, v.w);
                ap[j] = (ull)r0 | ((ull)r1 << 32);
            }
            nsum += __shfl_xor_sync(0xffffffffu, nsum, 1);
            if (h == 0) rn_s[row] = (t * TR + row < N) ? nsum : 3.4e38f;
        }
        __syncthreads();

        // ---- bf16 GEMM: warp computes m32 x n16 x k128 (32 mma) ----
        float c[2][2][4];
#pragma unroll
        for (int mf = 0; mf < 2; mf++)
#pragma unroll
            for (int nf2 = 0; nf2 < 2; nf2++)
#pragma unroll
                for (int q = 0; q < 4; q++) c[mf][nf2][q] = 0.f;

        const char* ap = abf + (wm * 32 + gid) * APITCH + t4 * 4;
#pragma unroll
        for (int ks = 0; ks < 8; ks++) {
            const int o = ks * 32;
            const unsigned a00 = *(const unsigned*)(ap + o);
            const unsigned a01 = *(const unsigned*)(ap + o + 8 * APITCH);
            const unsigned a02 = *(const unsigned*)(ap + o + 16);
            const unsigned a03 = *(const unsigned*)(ap + o + 8 * APITCH + 16);
            const unsigned a10 = *(const unsigned*)(ap + o + 16 * APITCH);
            const unsigned a11 = *(const unsigned*)(ap + o + 24 * APITCH);
            const unsigned a12 = *(const unsigned*)(ap + o + 16 * APITCH + 16);
            const unsigned a13 = *(const unsigned*)(ap + o + 24 * APITCH + 16);
            mma_bf16(c[0][0], a00, a01, a02, a03, b0r[ks][0], b1r[ks][0]);
            mma_bf16(c[0][1], a00, a01, a02, a03, b0r[ks][1], b1r[ks][1]);
            mma_bf16(c[1][0], a10, a11, a12, a13, b0r[ks][0], b1r[ks][0]);
            mma_bf16(c[1][1], a10, a11, a12, a13, b0r[ks][1], b1r[ks][1]);
        }

        // ---- epilogue: sq = an + rn - 2*dot into sq buffer ----
#pragma unroll
        for (int mf = 0; mf < 2; mf++) {
            const int R = wm * 32 + mf * 16 + gid;
            const float rn0 = rn_s[R], rn1 = rn_s[R + 8];
#pragma unroll
            for (int nf2 = 0; nf2 < 2; nf2++) {
                const int C = wn * 16 + nf2 * 8 + 2 * t4;
                const float an0 = an_s[C], an1 = an_s[C + 1];
                sq_s[C * 132 + R]           = an0 + rn0 - 2.f * c[mf][nf2][0];
                sq_s[(C + 1) * 132 + R]     = an1 + rn0 - 2.f * c[mf][nf2][1];
                sq_s[C * 132 + R + 8]       = an0 + rn1 - 2.f * c[mf][nf2][2];
                sq_s[(C + 1) * 132 + R + 8] = an1 + rn1 - 2.f * c[mf][nf2][3];
            }
        }
        __syncthreads();

        // ---- scan: thread (batch=lane, rowgroup=w) top-5 over 16 rows ----
        {
            const float* sp = sq_s + lane * 132 + w * 16;
            const int grow = t * TR + w * 16;
#pragma unroll
            for (int rr = 0; rr < 16; rr++)
                ins5(sp[rr], grow + rr, td, ti);
        }
        // no trailing sync needed: next iteration syncs before touching abf/sq_s

        ib = 1 - ib;
    }

    // ---- block merge: 8 group-lists per batch -> 5 (approx) ----
    float* md = (float*)(sm + OFF_STG);
    int*   mi = (int*)(sm + OFF_STG + 256 * 5 * 4);
    __syncthreads();
#pragma unroll
    for (int j = 0; j < 5; j++) { md[tid * 5 + j] = td[j]; mi[tid * 5 + j] = ti[j]; }
    __syncthreads();
    if (tid < 32) {
        float e[5]; int m[5];
#pragma unroll
        for (int j = 0; j < 5; j++) { e[j] = 3.4e38f; m[j] = 0; }
        for (int g = 0; g < 8; g++) {
            const int src = (g * 32 + tid) * 5;
#pragma unroll
            for (int j = 0; j < 5; j++) ins5(md[src + j], mi[src + j], e, m);
        }
        const int ob = (tid * GBLK + blockIdx.x) * K;
#pragma unroll
        for (int j = 0; j < 5; j++) { g_cand_d[ob + j] = e[j]; g_cand_i[ob + j] = m[j]; }
    }

    // ---- last-block exact refine + output (148 CTAs co-resident: one wave) ----
    __threadfence();
    __syncthreads();
    __shared__ unsigned rank_s;
    if (tid == 0) rank_s = atomicAdd(&g_done, 1u);
    __syncthreads();
    if (rank_s != GBLK - 1) return;

    float* ed  = (float*)(sm + OFF_STG);           // [256][8]
    int*   ei  = (int*)(ed + 2048);                // [256][8]
    float* fd  = (float*)(ei + 2048);              // [32][8]
    int*   fi  = (int*)(fd + 256);                 // [32][8]
    float* fsq = (float*)(fi + 256);               // [32][8]

    // phase 1: 8 threads/batch, strided scan of 740 approx candidates -> top-8 each
    {
        const int b = tid >> 3, s = tid & 7;
        float e8[8]; int m8[8];
#pragma unroll
        for (int j = 0; j < 8; j++) { e8[j] = 3.4e38f; m8[j] = 0; }
        const float* cd = g_cand_d + (size_t)b * GBLK * K;
        const int*   ci = g_cand_i + (size_t)b * GBLK * K;
        for (int c2 = s; c2 < GBLK * K; c2 += 8) ins8(cd[c2], ci[c2], e8, m8);
#pragma unroll
        for (int j = 0; j < 8; j++) { ed[tid * 8 + j] = e8[j]; ei[tid * 8 + j] = m8[j]; }
    }
    __syncthreads();

    // phase 2: one thread per batch merges 64 -> approx top-8
    if (tid < 32) {
        float e8[8]; int m8[8];
#pragma unroll
        for (int j = 0; j < 8; j++) { e8[j] = 3.4e38f; m8[j] = 0; }
        for (int s = 0; s < 8; s++) {
            const int src = (tid * 8 + s) * 8;
#pragma unroll
            for (int j = 0; j < 8; j++) ins8(ed[src + j], ei[src + j], e8, m8);
        }
#pragma unroll
        for (int j = 0; j < 8; j++) { fd[tid * 8 + j] = e8[j]; fi[tid * 8 + j] = m8[j]; }
    }
    __syncthreads();

    // phase 3: exact fp32 sq for each of the 8 candidates per batch
    {
        const int b = tid >> 3, s = tid & 7;
        const int idx = fi[b * 8 + s];
        const float4* rp = (const float4*)reps + (size_t)idx * 32;
        const float4* bp = (const float4*)g_brep + b * 32;
        float dot = 0.f, rn = 0.f;
#pragma unroll 8
        for (int k4 = 0; k4 < 32; k4++) {
            const float4 r = __ldg(rp + k4);
            const float4 a = bp[k4];
            dot = fmaf(a.x, r.x, dot); dot = fmaf(a.y, r.y, dot);
            dot = fmaf(a.z, r.z, dot); dot = fmaf(a.w, r.w, dot);
            rn  = fmaf(r.x, r.x, rn);  rn  = fmaf(r.y, r.y, rn);
            rn  = fmaf(r.z, r.z, rn);  rn  = fmaf(r.w, r.w, rn);
        }
        fsq[b * 8 + s] = an_s[b] + rn - 2.f * dot;
    }
    __syncthreads();

    // phase 4: exact top-5 of 8, sqrt, softmax, action gather
    if (tid < 32) {
        const int b = tid;
        float e[5]; int m[5];
#pragma unroll
        for (int j = 0; j < 5; j++) { e[j] = 3.4e38f; m[j] = 0; }
#pragma unroll
        for (int j = 0; j < 8; j++) ins5(fsq[b * 8 + j], fi[b * 8 + j], e, m);
        const float t0 = sqrtf(fmaxf(e[0], 1e-12f));
        const float t1 = sqrtf(fmaxf(e[1], 1e-12f));
        const float t2 = sqrtf(fmaxf(e[2], 1e-12f));
        const float t3 = sqrtf(fmaxf(e[3], 1e-12f));
        const float t4v = sqrtf(fmaxf(e[4], 1e-12f));
        const float dmin = t0;
        const float w0 = expf(dmin - t0);
        const float w1 = expf(dmin - t1);
        const float w2 = expf(dmin - t2);
        const float w3 = expf(dmin - t3);
        const float w4 = expf(dmin - t4v);
        const float inv = 1.f / (w0 + w1 + w2 + w3 + w4);
        const float* a0 = actions + (size_t)m[0] * A;
        const float* a1 = actions + (size_t)m[1] * A;
        const float* a2 = actions + (size_t)m[2] * A;
        const float* a3 = actions + (size_t)m[3] * A;
        const float* a4 = actions + (size_t)m[4] * A;
#pragma unroll
        for (int a = 0; a < A; a++)
            out[b * A + a] = (w0 * a0[a] + w1 * a1[a] + w2 * a2[a] +
                              w3 * a3[a] + w4 * a4[a]) * inv;
    }
    if (tid == 0) g_done = 0;
}

// ---------------- launch ----------------
extern "C" void kernel_launch(void* const* d_in, const int* in_sizes, int n_in,
                              void* d_out, int out_size)
{
    const float* x       = (const float*)d_in[0];
    const float* W       = (const float*)d_in[1];
    const float* b_enc   = (const float*)d_in[2];
    const float* reps    = (const float*)d_in[3];
    const float* actions = (const float*)d_in[4];
    const int N = in_sizes[3] / D;

    static int attr_done = 0;
    if (!attr_done) {
        cudaFuncSetAttribute(dist_topk_kernel,
                             cudaFuncAttributeMaxDynamicSharedMemorySize, SMEM_TOTAL);
        attr_done = 1;
    }

    enc_partial_kernel<<<dim3(KSPLIT, B / BT), 128>>>(x, W);
    enc_reduce_kernel<<<B, 128>>>(b_enc);
    dist_topk_kernel<<<GBLK, 256, SMEM_TOTAL>>>(reps, N, actions, (float*)d_out);
}